// round 1
// baseline (speedup 1.0000x reference)
#include <cuda_runtime.h>

// SpinorBilinears: psi [B=8, N=65536, S=4] f32, gamma [C=8, S=4, S=4] f32.
// Outputs (concatenated flat in d_out):
//   K0 [B*N]          = p.p
//   K1 [B*N, 8, 8]    = 0.5*(u_c.v_d - u_d.v_c)   (u_c = gamma_c^T p, v_c = gamma_c p)
//   K2 [B*N, 8, 8]    = 0.5*(u_c.v_d + u_d.v_c)
//
// HBM-store-bound (~270 MB written). One thread per token; outputs staged in
// swizzled shared memory and copied out with fully-coalesced float4 stores.

#define TPB 128

__device__ __forceinline__ float dot4(const float* a, const float* b) {
    return fmaf(a[0], b[0], fmaf(a[1], b[1], fmaf(a[2], b[2], a[3] * b[3])));
}

__global__ __launch_bounds__(TPB) void spinor_bilinears_kernel(
    const float* __restrict__ psi,
    const float* __restrict__ gamma,
    float* __restrict__ out,
    int BN)
{
    __shared__ float4 sg[32];            // gamma: 8 matrices x 4 rows, as float4
    __shared__ float  stage[TPB * 64];   // 32 KB staging for one [128 tokens x 64] matrix

    const int tid = threadIdx.x;
    if (tid < 32) sg[tid] = reinterpret_cast<const float4*>(gamma)[tid];
    __syncthreads();

    const int t = blockIdx.x * TPB + tid;   // token id; grid sized exactly BN/TPB

    // ---- load spinor (16B aligned, coalesced) ----
    const float4 p4 = reinterpret_cast<const float4*>(psi)[t];
    const float p[4] = {p4.x, p4.y, p4.z, p4.w};

    // ---- K0 (coalesced STG.32) ----
    out[t] = dot4(p, p);

    // ---- u_c = gamma_c^T p ; v_c = gamma_c p ----
    float u[8][4], v[8][4];
#pragma unroll
    for (int c = 0; c < 8; c++) {
        const float4 r0 = sg[c * 4 + 0];
        const float4 r1 = sg[c * 4 + 1];
        const float4 r2 = sg[c * 4 + 2];
        const float4 r3 = sg[c * 4 + 3];
        v[c][0] = fmaf(r0.x, p[0], fmaf(r0.y, p[1], fmaf(r0.z, p[2], r0.w * p[3])));
        v[c][1] = fmaf(r1.x, p[0], fmaf(r1.y, p[1], fmaf(r1.z, p[2], r1.w * p[3])));
        v[c][2] = fmaf(r2.x, p[0], fmaf(r2.y, p[1], fmaf(r2.z, p[2], r2.w * p[3])));
        v[c][3] = fmaf(r3.x, p[0], fmaf(r3.y, p[1], fmaf(r3.z, p[2], r3.w * p[3])));
        u[c][0] = fmaf(r0.x, p[0], fmaf(r1.x, p[1], fmaf(r2.x, p[2], r3.x * p[3])));
        u[c][1] = fmaf(r0.y, p[0], fmaf(r1.y, p[1], fmaf(r2.y, p[2], r3.y * p[3])));
        u[c][2] = fmaf(r0.z, p[0], fmaf(r1.z, p[1], fmaf(r2.z, p[2], r3.z * p[3])));
        u[c][3] = fmaf(r0.w, p[0], fmaf(r1.w, p[1], fmaf(r2.w, p[2], r3.w * p[3])));
    }

    const size_t bn      = (size_t)BN;
    const size_t blkBase = (size_t)blockIdx.x * (size_t)(TPB * 64);
    const int    sw      = tid & 15;     // float4-granular XOR swizzle key

    // ================= K1 (antisymmetric) =================
#pragma unroll
    for (int c = 0; c < 8; c++) {
#pragma unroll
        for (int d4 = 0; d4 < 2; d4++) {
            float4 row;
            {
                const int d = d4 * 4;
                row.x = 0.5f * (dot4(u[c], v[d + 0]) - dot4(u[d + 0], v[c]));
                row.y = 0.5f * (dot4(u[c], v[d + 1]) - dot4(u[d + 1], v[c]));
                row.z = 0.5f * (dot4(u[c], v[d + 2]) - dot4(u[d + 2], v[c]));
                row.w = 0.5f * (dot4(u[c], v[d + 3]) - dot4(u[d + 3], v[c]));
            }
            const int e4 = c * 2 + d4;                              // 0..15
            *reinterpret_cast<float4*>(&stage[tid * 64 + ((e4 ^ sw) << 2)]) = row;
        }
    }
    __syncthreads();

    {
        float* __restrict__ dst = out + bn + blkBase;
#pragma unroll
        for (int it = 0; it < 16; it++) {
            const int o   = it * (TPB * 4) + tid * 4;   // float offset in block's 8192-float region
            const int tok = o >> 6;
            const int e4  = (o >> 2) & 15;
            const float4 val =
                *reinterpret_cast<const float4*>(&stage[tok * 64 + ((e4 ^ (tok & 15)) << 2)]);
            *reinterpret_cast<float4*>(&dst[o]) = val;
        }
    }
    __syncthreads();

    // ================= K2 (symmetric) =================
#pragma unroll
    for (int c = 0; c < 8; c++) {
#pragma unroll
        for (int d4 = 0; d4 < 2; d4++) {
            float4 row;
            {
                const int d = d4 * 4;
                row.x = 0.5f * (dot4(u[c], v[d + 0]) + dot4(u[d + 0], v[c]));
                row.y = 0.5f * (dot4(u[c], v[d + 1]) + dot4(u[d + 1], v[c]));
                row.z = 0.5f * (dot4(u[c], v[d + 2]) + dot4(u[d + 2], v[c]));
                row.w = 0.5f * (dot4(u[c], v[d + 3]) + dot4(u[d + 3], v[c]));
            }
            const int e4 = c * 2 + d4;
            *reinterpret_cast<float4*>(&stage[tid * 64 + ((e4 ^ sw) << 2)]) = row;
        }
    }
    __syncthreads();

    {
        float* __restrict__ dst = out + bn + bn * 64 + blkBase;
#pragma unroll
        for (int it = 0; it < 16; it++) {
            const int o   = it * (TPB * 4) + tid * 4;
            const int tok = o >> 6;
            const int e4  = (o >> 2) & 15;
            const float4 val =
                *reinterpret_cast<const float4*>(&stage[tok * 64 + ((e4 ^ (tok & 15)) << 2)]);
            *reinterpret_cast<float4*>(&dst[o]) = val;
        }
    }
}

extern "C" void kernel_launch(void* const* d_in, const int* in_sizes, int n_in,
                              void* d_out, int out_size) {
    const float* psi   = (const float*)d_in[0];   // [B, N, S]  f32
    const float* gamma = (const float*)d_in[1];   // [C, S, S]  f32
    float* out = (float*)d_out;

    const int BN = in_sizes[0] / 4;               // B*N tokens (S = 4)
    const int grid = BN / TPB;                    // 524288 / 128 = 4096, exact

    spinor_bilinears_kernel<<<grid, TPB>>>(psi, gamma, out, BN);
}

// round 2
// speedup vs baseline: 1.0054x; 1.0054x over previous
#include <cuda_runtime.h>

// SpinorBilinears: psi [B=8, N=65536, S=4] f32, gamma [C=8, S=4, S=4] f32.
// Outputs (concatenated flat in d_out):
//   K0 [B*N]          = p.p
//   K1 [B*N, 8, 8]    = 0.5*(u_c.v_d - u_d.v_c)   (u_c = gamma_c^T p, v_c = gamma_c p)
//   K2 [B*N, 8, 8]    = 0.5*(u_c.v_d + u_d.v_c)
//
// HBM-store-bound (~270 MB written). One thread per token; outputs staged in
// swizzled shared memory and copied out with fully-coalesced float4 stores.

#define TPB 128

__device__ __forceinline__ float dot4(const float* a, const float* b) {
    return fmaf(a[0], b[0], fmaf(a[1], b[1], fmaf(a[2], b[2], a[3] * b[3])));
}

__global__ __launch_bounds__(TPB) void spinor_bilinears_kernel(
    const float* __restrict__ psi,
    const float* __restrict__ gamma,
    float* __restrict__ out,
    int BN)
{
    __shared__ float4 sg[32];            // gamma: 8 matrices x 4 rows, as float4
    __shared__ float  stage[TPB * 64];   // 32 KB staging for one [128 tokens x 64] matrix

    const int tid = threadIdx.x;
    if (tid < 32) sg[tid] = reinterpret_cast<const float4*>(gamma)[tid];
    __syncthreads();

    const int t = blockIdx.x * TPB + tid;   // token id; grid sized exactly BN/TPB

    // ---- load spinor (16B aligned, coalesced) ----
    const float4 p4 = reinterpret_cast<const float4*>(psi)[t];
    const float p[4] = {p4.x, p4.y, p4.z, p4.w};

    // ---- K0 (coalesced STG.32) ----
    out[t] = dot4(p, p);

    // ---- u_c = gamma_c^T p ; v_c = gamma_c p ----
    float u[8][4], v[8][4];
#pragma unroll
    for (int c = 0; c < 8; c++) {
        const float4 r0 = sg[c * 4 + 0];
        const float4 r1 = sg[c * 4 + 1];
        const float4 r2 = sg[c * 4 + 2];
        const float4 r3 = sg[c * 4 + 3];
        v[c][0] = fmaf(r0.x, p[0], fmaf(r0.y, p[1], fmaf(r0.z, p[2], r0.w * p[3])));
        v[c][1] = fmaf(r1.x, p[0], fmaf(r1.y, p[1], fmaf(r1.z, p[2], r1.w * p[3])));
        v[c][2] = fmaf(r2.x, p[0], fmaf(r2.y, p[1], fmaf(r2.z, p[2], r2.w * p[3])));
        v[c][3] = fmaf(r3.x, p[0], fmaf(r3.y, p[1], fmaf(r3.z, p[2], r3.w * p[3])));
        u[c][0] = fmaf(r0.x, p[0], fmaf(r1.x, p[1], fmaf(r2.x, p[2], r3.x * p[3])));
        u[c][1] = fmaf(r0.y, p[0], fmaf(r1.y, p[1], fmaf(r2.y, p[2], r3.y * p[3])));
        u[c][2] = fmaf(r0.z, p[0], fmaf(r1.z, p[1], fmaf(r2.z, p[2], r3.z * p[3])));
        u[c][3] = fmaf(r0.w, p[0], fmaf(r1.w, p[1], fmaf(r2.w, p[2], r3.w * p[3])));
    }

    const size_t bn      = (size_t)BN;
    const size_t blkBase = (size_t)blockIdx.x * (size_t)(TPB * 64);
    const int    sw      = tid & 15;     // float4-granular XOR swizzle key

    // ================= K1 (antisymmetric) =================
#pragma unroll
    for (int c = 0; c < 8; c++) {
#pragma unroll
        for (int d4 = 0; d4 < 2; d4++) {
            float4 row;
            {
                const int d = d4 * 4;
                row.x = 0.5f * (dot4(u[c], v[d + 0]) - dot4(u[d + 0], v[c]));
                row.y = 0.5f * (dot4(u[c], v[d + 1]) - dot4(u[d + 1], v[c]));
                row.z = 0.5f * (dot4(u[c], v[d + 2]) - dot4(u[d + 2], v[c]));
                row.w = 0.5f * (dot4(u[c], v[d + 3]) - dot4(u[d + 3], v[c]));
            }
            const int e4 = c * 2 + d4;                              // 0..15
            *reinterpret_cast<float4*>(&stage[tid * 64 + ((e4 ^ sw) << 2)]) = row;
        }
    }
    __syncthreads();

    {
        float* __restrict__ dst = out + bn + blkBase;
#pragma unroll
        for (int it = 0; it < 16; it++) {
            const int o   = it * (TPB * 4) + tid * 4;   // float offset in block's 8192-float region
            const int tok = o >> 6;
            const int e4  = (o >> 2) & 15;
            const float4 val =
                *reinterpret_cast<const float4*>(&stage[tok * 64 + ((e4 ^ (tok & 15)) << 2)]);
            *reinterpret_cast<float4*>(&dst[o]) = val;
        }
    }
    __syncthreads();

    // ================= K2 (symmetric) =================
#pragma unroll
    for (int c = 0; c < 8; c++) {
#pragma unroll
        for (int d4 = 0; d4 < 2; d4++) {
            float4 row;
            {
                const int d = d4 * 4;
                row.x = 0.5f * (dot4(u[c], v[d + 0]) + dot4(u[d + 0], v[c]));
                row.y = 0.5f * (dot4(u[c], v[d + 1]) + dot4(u[d + 1], v[c]));
                row.z = 0.5f * (dot4(u[c], v[d + 2]) + dot4(u[d + 2], v[c]));
                row.w = 0.5f * (dot4(u[c], v[d + 3]) + dot4(u[d + 3], v[c]));
            }
            const int e4 = c * 2 + d4;
            *reinterpret_cast<float4*>(&stage[tid * 64 + ((e4 ^ sw) << 2)]) = row;
        }
    }
    __syncthreads();

    {
        float* __restrict__ dst = out + bn + bn * 64 + blkBase;
#pragma unroll
        for (int it = 0; it < 16; it++) {
            const int o   = it * (TPB * 4) + tid * 4;
            const int tok = o >> 6;
            const int e4  = (o >> 2) & 15;
            const float4 val =
                *reinterpret_cast<const float4*>(&stage[tok * 64 + ((e4 ^ (tok & 15)) << 2)]);
            *reinterpret_cast<float4*>(&dst[o]) = val;
        }
    }
}

extern "C" void kernel_launch(void* const* d_in, const int* in_sizes, int n_in,
                              void* d_out, int out_size) {
    const float* psi   = (const float*)d_in[0];   // [B, N, S]  f32
    const float* gamma = (const float*)d_in[1];   // [C, S, S]  f32
    float* out = (float*)d_out;

    const int BN = in_sizes[0] / 4;               // B*N tokens (S = 4)
    const int grid = BN / TPB;                    // 524288 / 128 = 4096, exact

    spinor_bilinears_kernel<<<grid, TPB>>>(psi, gamma, out, BN);
}

// round 3
// speedup vs baseline: 1.0101x; 1.0047x over previous
#include <cuda_runtime.h>

// SpinorBilinears: psi [B=8, N=65536, S=4] f32, gamma [C=8, S=4, S=4] f32.
// Outputs (concatenated flat in d_out):
//   K0 [B*N]          = p.p
//   K1 [B*N, 8, 8]    = 0.5*(u_c.v_d - u_d.v_c)   (u_c = gamma_c^T p, v_c = gamma_c p)
//   K2 [B*N, 8, 8]    = 0.5*(u_c.v_d + u_d.v_c)
//
// HBM-store-bound (~270 MB written). One thread per token; outputs staged in
// swizzled shared memory and copied out with fully-coalesced float4 stores.

#define TPB 128

__device__ __forceinline__ float dot4(const float* a, const float* b) {
    return fmaf(a[0], b[0], fmaf(a[1], b[1], fmaf(a[2], b[2], a[3] * b[3])));
}

__global__ __launch_bounds__(TPB) void spinor_bilinears_kernel(
    const float* __restrict__ psi,
    const float* __restrict__ gamma,
    float* __restrict__ out,
    int BN)
{
    __shared__ float4 sg[32];            // gamma: 8 matrices x 4 rows, as float4
    __shared__ float  stage[TPB * 64];   // 32 KB staging for one [128 tokens x 64] matrix

    const int tid = threadIdx.x;
    if (tid < 32) sg[tid] = reinterpret_cast<const float4*>(gamma)[tid];
    __syncthreads();

    const int t = blockIdx.x * TPB + tid;   // token id; grid sized exactly BN/TPB

    // ---- load spinor (16B aligned, coalesced) ----
    const float4 p4 = reinterpret_cast<const float4*>(psi)[t];
    const float p[4] = {p4.x, p4.y, p4.z, p4.w};

    // ---- K0 (coalesced STG.32) ----
    out[t] = dot4(p, p);

    // ---- u_c = gamma_c^T p ; v_c = gamma_c p ----
    float u[8][4], v[8][4];
#pragma unroll
    for (int c = 0; c < 8; c++) {
        const float4 r0 = sg[c * 4 + 0];
        const float4 r1 = sg[c * 4 + 1];
        const float4 r2 = sg[c * 4 + 2];
        const float4 r3 = sg[c * 4 + 3];
        v[c][0] = fmaf(r0.x, p[0], fmaf(r0.y, p[1], fmaf(r0.z, p[2], r0.w * p[3])));
        v[c][1] = fmaf(r1.x, p[0], fmaf(r1.y, p[1], fmaf(r1.z, p[2], r1.w * p[3])));
        v[c][2] = fmaf(r2.x, p[0], fmaf(r2.y, p[1], fmaf(r2.z, p[2], r2.w * p[3])));
        v[c][3] = fmaf(r3.x, p[0], fmaf(r3.y, p[1], fmaf(r3.z, p[2], r3.w * p[3])));
        u[c][0] = fmaf(r0.x, p[0], fmaf(r1.x, p[1], fmaf(r2.x, p[2], r3.x * p[3])));
        u[c][1] = fmaf(r0.y, p[0], fmaf(r1.y, p[1], fmaf(r2.y, p[2], r3.y * p[3])));
        u[c][2] = fmaf(r0.z, p[0], fmaf(r1.z, p[1], fmaf(r2.z, p[2], r3.z * p[3])));
        u[c][3] = fmaf(r0.w, p[0], fmaf(r1.w, p[1], fmaf(r2.w, p[2], r3.w * p[3])));
    }

    const size_t bn      = (size_t)BN;
    const size_t blkBase = (size_t)blockIdx.x * (size_t)(TPB * 64);
    const int    sw      = tid & 15;     // float4-granular XOR swizzle key

    // ================= K1 (antisymmetric) =================
#pragma unroll
    for (int c = 0; c < 8; c++) {
#pragma unroll
        for (int d4 = 0; d4 < 2; d4++) {
            float4 row;
            {
                const int d = d4 * 4;
                row.x = 0.5f * (dot4(u[c], v[d + 0]) - dot4(u[d + 0], v[c]));
                row.y = 0.5f * (dot4(u[c], v[d + 1]) - dot4(u[d + 1], v[c]));
                row.z = 0.5f * (dot4(u[c], v[d + 2]) - dot4(u[d + 2], v[c]));
                row.w = 0.5f * (dot4(u[c], v[d + 3]) - dot4(u[d + 3], v[c]));
            }
            const int e4 = c * 2 + d4;                              // 0..15
            *reinterpret_cast<float4*>(&stage[tid * 64 + ((e4 ^ sw) << 2)]) = row;
        }
    }
    __syncthreads();

    {
        float* __restrict__ dst = out + bn + blkBase;
#pragma unroll
        for (int it = 0; it < 16; it++) {
            const int o   = it * (TPB * 4) + tid * 4;   // float offset in block's 8192-float region
            const int tok = o >> 6;
            const int e4  = (o >> 2) & 15;
            const float4 val =
                *reinterpret_cast<const float4*>(&stage[tok * 64 + ((e4 ^ (tok & 15)) << 2)]);
            *reinterpret_cast<float4*>(&dst[o]) = val;
        }
    }
    __syncthreads();

    // ================= K2 (symmetric) =================
#pragma unroll
    for (int c = 0; c < 8; c++) {
#pragma unroll
        for (int d4 = 0; d4 < 2; d4++) {
            float4 row;
            {
                const int d = d4 * 4;
                row.x = 0.5f * (dot4(u[c], v[d + 0]) + dot4(u[d + 0], v[c]));
                row.y = 0.5f * (dot4(u[c], v[d + 1]) + dot4(u[d + 1], v[c]));
                row.z = 0.5f * (dot4(u[c], v[d + 2]) + dot4(u[d + 2], v[c]));
                row.w = 0.5f * (dot4(u[c], v[d + 3]) + dot4(u[d + 3], v[c]));
            }
            const int e4 = c * 2 + d4;
            *reinterpret_cast<float4*>(&stage[tid * 64 + ((e4 ^ sw) << 2)]) = row;
        }
    }
    __syncthreads();

    {
        float* __restrict__ dst = out + bn + bn * 64 + blkBase;
#pragma unroll
        for (int it = 0; it < 16; it++) {
            const int o   = it * (TPB * 4) + tid * 4;
            const int tok = o >> 6;
            const int e4  = (o >> 2) & 15;
            const float4 val =
                *reinterpret_cast<const float4*>(&stage[tok * 64 + ((e4 ^ (tok & 15)) << 2)]);
            *reinterpret_cast<float4*>(&dst[o]) = val;
        }
    }
}

extern "C" void kernel_launch(void* const* d_in, const int* in_sizes, int n_in,
                              void* d_out, int out_size) {
    const float* psi   = (const float*)d_in[0];   // [B, N, S]  f32
    const float* gamma = (const float*)d_in[1];   // [C, S, S]  f32
    float* out = (float*)d_out;

    const int BN = in_sizes[0] / 4;               // B*N tokens (S = 4)
    const int grid = BN / TPB;                    // 524288 / 128 = 4096, exact

    spinor_bilinears_kernel<<<grid, TPB>>>(psi, gamma, out, BN);
}